// round 15
// baseline (speedup 1.0000x reference)
#include <cuda_runtime.h>
#include <cuda_bf16.h>
#include <mma.h>
#include <cstdint>

using namespace nvcuda;
typedef __nv_bfloat16 bf16;

#define OFF_H0 0
#define OFF_H1 1048576            // 1024*1024
#define OFF_H2 1310720            // +1024*256
#define OFF_H3 1376256            // +1024*16
// total used: 1376256 + 1024*16 = 1392640

__device__ __align__(1024) bf16  g_H[1392640];
__device__ float g_sumexp[4096];
__device__ float g_cl[3072];      // head logits for cols 20000..20002 (cluster)

__device__ __forceinline__ void cp16s(bf16* dst, const bf16* src) {
    unsigned d = (unsigned)__cvta_generic_to_shared(dst);
    asm volatile("cp.async.cg.shared.global [%0], [%1], 16;" :: "r"(d), "l"(src));
}
#define CP_COMMIT() asm volatile("cp.async.commit_group;")
template<int N> __device__ __forceinline__ void cp_wait() {
    asm volatile("cp.async.wait_group %0;" :: "n"(N));
}

// ---------------------------------------------------------------------------
// Barrier-free weight-stationary vocab GEMM + fused exp-sum (device body).
//   NB vocab rows per block; W slab + bias resident in smem (one barrier).
//   512 threads = 16 warps, WM x WN (WN=NB/64); warp tile 32 x 64 (acc[2][4]).
//   A staged per KC chunk into a WARP-PRIVATE S-stage ring of smem buffers via
//   per-warp cp.async (wait_group/commit are per-thread; __syncwarp publishes
//   copied data warp-wide). S-1 chunks of prefetch depth cover L2 latency.
//   Registers pin occupancy to 1 CTA/SM, so large smem is free.
//   Epilogue: register-resident exp+bias on mma.16816 accumulator layout,
//   quad shfl-reduce, one atomicAdd per row. Head block n0=19968 also writes
//   cols 20000..20002 logits to g_cl (cluster logits for finalize).
// smem: bias[NB] | Bs[NB x (K+8)] | Stage[16w x S x 32 x (KC+8)]
// ---------------------------------------------------------------------------
template<int K, int NB, int MS, int S>
__device__ __forceinline__ void vocab_body(
        int bx, int by, char* smem,
        int h_off, const float* __restrict__ W, const float* __restrict__ W2,
        const float* __restrict__ bias, const float* __restrict__ bias2,
        int split, int V, int cidx)
{
    constexpr int KP    = K + 8;
    constexpr int WN    = NB / 64;            // 1 or 2
    constexpr int WM    = 16 / WN;            // 16 or 8
    constexpr int ROWS  = WM * 32;            // tokens per pass
    constexpr int NPASS = 1024 / ROWS;
    constexpr int PPB   = NPASS / MS;         // passes per block
    constexpr int KC    = (K >= 32) ? 32 : 16;
    constexpr int NCH   = K / KC;
    constexpr int KP2   = KC + 8;
    constexpr int CPL   = KC / 8;             // cp.async per lane per chunk
    constexpr int QR    = KC / 8;             // uint4 per 16B-elems row
    constexpr int TOTAL = PPB * NCH;          // chunks per block

    float* bias_s = (float*)smem;
    bf16*  Bs     = (bf16*)(smem + NB * 4);
    bf16*  Stage  = (bf16*)(smem + NB * 4 + NB * KP * 2);

    const int tid = threadIdx.x, wid = tid >> 5, lane = tid & 31;
    const int wm = wid / WN, wn = wid % WN;
    const int n0 = bx * NB;
    const bf16* __restrict__ H = g_H + h_off;

    bf16* stg_base = Stage + wid * S * 32 * KP2;

    auto issue_chunk = [&](int gc) {
        int pass = by * PPB + gc / NCH;
        int ch   = gc % NCH;
        bf16* dst = stg_base + (gc % S) * 32 * KP2;
        const bf16* src = H + (size_t)(pass * ROWS + wm * 32) * K + ch * KC;
        #pragma unroll
        for (int i = 0; i < CPL; i++) {
            int idx = lane + i * 32;
            int r = idx / QR, q = idx % QR;
            cp16s(dst + r * KP2 + q * 8, src + (size_t)r * K + q * 8);
        }
        CP_COMMIT();
    };
    #pragma unroll
    for (int s = 0; s < S; s++) {
        if (s < TOTAL) issue_chunk(s);
        else           CP_COMMIT();
    }

    if (tid < NB) {
        int v = n0 + tid;
        float bv = 0.0f;
        if (v < split)  bv = bias[v];
        else if (v < V) bv = bias2[v - split];
        bias_s[tid] = bv;
    }
    // weight slab fp32 -> bf16 (once per block)
    for (int idx = tid; idx < NB * K / 4; idx += 512) {
        int r = idx / (K / 4), q = idx % (K / 4);
        int v = n0 + r;
        float4 val = make_float4(0.f, 0.f, 0.f, 0.f);
        if (v < split)  val = *(const float4*)(W + (size_t)v * K + q * 4);
        else if (v < V) val = *(const float4*)(W2 + (size_t)(v - split) * K + q * 4);
        __nv_bfloat162 lo = __floats2bfloat162_rn(val.x, val.y);
        __nv_bfloat162 hi = __floats2bfloat162_rn(val.z, val.w);
        uint2 pk; pk.x = *(unsigned*)&lo; pk.y = *(unsigned*)&hi;
        *(uint2*)(Bs + r * KP + q * 4) = pk;
    }
    __syncthreads();   // the only block-wide barrier

    const int qrow = lane >> 2;          // 0..7
    const int c2   = (lane & 3) * 2;

    for (int pp = 0; pp < PPB; pp++) {
        const int m0 = (by * PPB + pp) * ROWS + wm * 32;

        wmma::fragment<wmma::accumulator, 16, 16, 16, float> acc[2][4];
        #pragma unroll
        for (int i = 0; i < 2; i++)
            #pragma unroll
            for (int j = 0; j < 4; j++) wmma::fill_fragment(acc[i][j], 0.0f);

        for (int ch = 0; ch < NCH; ch++) {
            const int gc = pp * NCH + ch;
            cp_wait<S - 1>();    // chunk gc complete (in-order groups)
            __syncwarp();        // publish copied smem warp-wide
            const bf16* stg = stg_base + (gc % S) * 32 * KP2;

            #pragma unroll
            for (int ksl = 0; ksl < KC / 16; ksl++) {
                wmma::fragment<wmma::matrix_a, 16, 16, 16, bf16, wmma::row_major> af[2];
                #pragma unroll
                for (int i = 0; i < 2; i++)
                    wmma::load_matrix_sync(af[i], stg + (i * 16) * KP2 + ksl * 16, KP2);
                #pragma unroll
                for (int j = 0; j < 4; j++) {
                    wmma::fragment<wmma::matrix_b, 16, 16, 16, bf16, wmma::col_major> bfr;
                    wmma::load_matrix_sync(bfr,
                        Bs + (wn * 64 + j * 16) * KP + ch * KC + ksl * 16, KP);
                    #pragma unroll
                    for (int i = 0; i < 2; i++)
                        wmma::mma_sync(acc[i][j], af[i], bfr, acc[i][j]);
                }
            }
            __syncwarp();        // LDSMs done before buffer reuse
            if (gc + S < TOTAL) issue_chunk(gc + S);
            else                CP_COMMIT();   // keep group counting uniform
        }

        // register-resident epilogue: exp + bias on fragment regs, quad reduce
        #pragma unroll
        for (int i = 0; i < 2; i++) {
            float sA = 0.0f, sB = 0.0f;   // rows qrow, qrow+8 of this 16-tile
            #pragma unroll
            for (int j = 0; j < 4; j++) {
                const float* x = acc[i][j].x;
                int cb = wn * 64 + j * 16 + c2;
                if (n0 + cb < V) {
                    float b = bias_s[cb];
                    sA += __expf(x[0] + b); sB += __expf(x[2] + b);
                }
                if (n0 + cb + 1 < V) {
                    float b = bias_s[cb + 1];
                    sA += __expf(x[1] + b); sB += __expf(x[3] + b);
                }
                if (n0 + cb + 8 < V) {
                    float b = bias_s[cb + 8];
                    sA += __expf(x[4] + b); sB += __expf(x[6] + b);
                }
                if (n0 + cb + 9 < V) {
                    float b = bias_s[cb + 9];
                    sA += __expf(x[5] + b); sB += __expf(x[7] + b);
                }
            }
            sA += __shfl_xor_sync(0xffffffffu, sA, 1);
            sA += __shfl_xor_sync(0xffffffffu, sA, 2);
            sB += __shfl_xor_sync(0xffffffffu, sB, 1);
            sB += __shfl_xor_sync(0xffffffffu, sB, 2);
            if ((lane & 3) == 0) {
                atomicAdd(&g_sumexp[cidx * 1024 + m0 + i * 16 + qrow], sA);
                atomicAdd(&g_sumexp[cidx * 1024 + m0 + i * 16 + qrow + 8], sB);
            }
        }

        // cluster-logit extraction (head block covering cols 20000..20002 only)
        if (cidx == 0 && n0 == 19968) {
            #pragma unroll
            for (int i = 0; i < 2; i++) {
                int r0 = m0 + i * 16 + qrow, r1 = r0 + 8;
                #pragma unroll
                for (int j = 0; j < 4; j++) {
                    const float* x = acc[i][j].x;
                    int cb = wn * 64 + j * 16 + c2;
                    int g = n0 + cb;
                    #pragma unroll
                    for (int t = 0; t < 4; t++) {
                        static const int co[4] = {0, 1, 8, 9};
                        int gc2 = g + co[t];
                        if (gc2 >= 20000 && gc2 < 20003) {
                            int s = gc2 - 20000;
                            g_cl[s * 1024 + r0] = x[t < 2 ? t : t + 2] + bias_s[cb + co[t]];
                            g_cl[s * 1024 + r1] = x[t < 2 ? t + 2 : t + 4] + bias_s[cb + co[t]];
                        }
                    }
                }
            }
        }
    }
}

// Fused launch 1: head (626 CTAs, longest, launched first) + tail1 (314 CTAs)
__global__ __launch_bounds__(512) void vocab_big(
        const float* __restrict__ head_w, const float* __restrict__ cluster_w,
        const float* __restrict__ head_b, const float* __restrict__ cluster_b,
        const float* __restrict__ w1, const float* __restrict__ b1)
{
    extern __shared__ char smem[];
    int bx = blockIdx.x;
    if (bx < 626) {
        vocab_body<1024, 64, 2, 2>(bx % 313, bx / 313, smem, OFF_H0,
                                   head_w, cluster_w, head_b, cluster_b,
                                   20000, 20003, 0);
    } else {
        int b = bx - 626;
        vocab_body<256, 128, 2, 3>(b % 157, b / 157, smem, OFF_H1,
                                   w1, w1, b1, b1, 20000, 20000, 1);
    }
}

// Fused launch 2: tail2 (1250 CTAs) + tail3 (530 CTAs)
__global__ __launch_bounds__(512) void vocab_small(
        const float* __restrict__ w2, const float* __restrict__ b2,
        const float* __restrict__ w3, const float* __restrict__ b3)
{
    extern __shared__ char smem[];
    int bx = blockIdx.x;
    if (bx < 1250) {
        vocab_body<64, 128, 1, 4>(bx, 0, smem, OFF_H2,
                                  w2, w2, b2, b2, 160000, 160000, 2);
    } else {
        vocab_body<16, 128, 1, 4>(bx - 1250, 0, smem, OFF_H3,
                                  w3, w3, b3, b3, 67735, 67735, 3);
    }
}

// ---------------------------------------------------------------------------
// Fused projection GEMM (block (0,0) also zeroes g_sumexp).
// ---------------------------------------------------------------------------
#define AP 40
#define BPP 72
#define CPJ 68

__global__ __launch_bounds__(256) void proj_kernel(const float* __restrict__ A,
        const float* __restrict__ P0, const float* __restrict__ P1,
        const float* __restrict__ P2, const float* __restrict__ P3)
{
    __shared__ __align__(16) float s_c[128 * CPJ];
    bf16* As = (bf16*)s_c;
    bf16* Bs = As + 128 * AP;

    if (blockIdx.x == 0 && blockIdx.y == 0) {
        #pragma unroll
        for (int i = 0; i < 16; i++) g_sumexp[threadIdx.x + i * 256] = 0.0f;
    }

    int bx = blockIdx.x;
    const float* B; int Nout, h_off, n0;
    if (bx < 16)       { B = P0; Nout = 1024; h_off = OFF_H0; n0 = bx * 64; }
    else if (bx < 20)  { B = P1; Nout = 256;  h_off = OFF_H1; n0 = (bx - 16) * 64; }
    else if (bx == 20) { B = P2; Nout = 64;   h_off = OFF_H2; n0 = 0; }
    else               { B = P3; Nout = 16;   h_off = OFF_H3; n0 = 0; }

    const int tid = threadIdx.x;
    const int warpId = tid >> 5;
    const int wm = warpId & 3, wn = warpId >> 2;
    const int m0 = blockIdx.y * 128;
    const int K = 1024;

    wmma::fragment<wmma::accumulator, 16, 16, 16, float> acc[2][2];
    #pragma unroll
    for (int i = 0; i < 2; i++)
        #pragma unroll
        for (int j = 0; j < 2; j++) wmma::fill_fragment(acc[i][j], 0.0f);

    for (int kt = 0; kt < K; kt += 32) {
        #pragma unroll
        for (int i = 0; i < 4; i++) {
            int idx = tid + i * 256;
            int r = idx >> 3, kq = (idx & 7) << 2;
            float4 v = *(const float4*)(A + (size_t)(m0 + r) * K + kt + kq);
            bf16* d = As + r * AP + kq;
            d[0] = __float2bfloat16(v.x); d[1] = __float2bfloat16(v.y);
            d[2] = __float2bfloat16(v.z); d[3] = __float2bfloat16(v.w);
        }
        #pragma unroll
        for (int i = 0; i < 2; i++) {
            int idx = tid + i * 256;
            int kr = idx >> 4, nq = (idx & 15) << 2;
            int n = n0 + nq;
            float4 v = make_float4(0.f, 0.f, 0.f, 0.f);
            if (n < Nout) v = *(const float4*)(B + (size_t)(kt + kr) * Nout + n);
            bf16* d = Bs + kr * BPP + nq;
            d[0] = __float2bfloat16(v.x); d[1] = __float2bfloat16(v.y);
            d[2] = __float2bfloat16(v.z); d[3] = __float2bfloat16(v.w);
        }
        __syncthreads();
        #pragma unroll
        for (int kk = 0; kk < 32; kk += 16) {
            wmma::fragment<wmma::matrix_a, 16, 16, 16, bf16, wmma::row_major> af[2];
            wmma::fragment<wmma::matrix_b, 16, 16, 16, bf16, wmma::row_major> bfr[2];
            #pragma unroll
            for (int i = 0; i < 2; i++)
                wmma::load_matrix_sync(af[i], As + (wm * 32 + i * 16) * AP + kk, AP);
            #pragma unroll
            for (int j = 0; j < 2; j++)
                wmma::load_matrix_sync(bfr[j], Bs + kk * BPP + wn * 32 + j * 16, BPP);
            #pragma unroll
            for (int i = 0; i < 2; i++)
                #pragma unroll
                for (int j = 0; j < 2; j++)
                    wmma::mma_sync(acc[i][j], af[i], bfr[j], acc[i][j]);
        }
        __syncthreads();
    }

    #pragma unroll
    for (int i = 0; i < 2; i++)
        #pragma unroll
        for (int j = 0; j < 2; j++)
            wmma::store_matrix_sync(s_c + (wm * 32 + i * 16) * CPJ + wn * 32 + j * 16,
                                    acc[i][j], CPJ, wmma::mem_row_major);
    __syncthreads();

    bf16* Hh = g_H + h_off;
    for (int idx = tid; idx < 128 * 64; idx += 256) {
        int r = idx >> 6, c = idx & 63;
        int n = n0 + c;
        if (n < Nout)
            Hh[(size_t)(m0 + r) * Nout + n] = __float2bfloat16(s_c[r * CPJ + c]);
    }
}

// ---------------------------------------------------------------------------
// Finalize: per-row target logit + combine with logsumexps. One warp per row.
// Cluster logits come precomputed from the head GEMM (g_cl).
// ---------------------------------------------------------------------------
__device__ __forceinline__ float wdot(const bf16* h, const float* w, int K, int lane) {
    float s = 0.0f;
    #pragma unroll 8
    for (int k = lane; k < K; k += 32)
        s += __bfloat162float(h[k]) * w[k];
    #pragma unroll
    for (int o = 16; o; o >>= 1) s += __shfl_xor_sync(0xffffffffu, s, o);
    return s;
}

__global__ __launch_bounds__(256) void finalize_kernel(const int* __restrict__ target,
    const float* __restrict__ head_w,   const float* __restrict__ head_b,
    const float* __restrict__ w1, const float* __restrict__ b1,
    const float* __restrict__ w2, const float* __restrict__ b2,
    const float* __restrict__ w3, const float* __restrict__ b3,
    float* __restrict__ out)
{
    int warpId = threadIdx.x >> 5, lane = threadIdx.x & 31;
    int row = blockIdx.x * 8 + warpId;
    if (row >= 1024) return;

    const bf16* h0 = g_H + (size_t)row * 1024;

    float lse0 = logf(g_sumexp[row]);
    int t = target[row];
    float lp;
    if (t < 20000) {
        float s = wdot(h0, head_w + (size_t)t * 1024, 1024, lane) + head_b[t];
        lp = s - lse0;
    } else if (t < 40000) {
        int ti = t - 20000;
        const bf16* h = g_H + OFF_H1 + (size_t)row * 256;
        float s = wdot(h, w1 + (size_t)ti * 256, 256, lane) + b1[ti];
        lp = (g_cl[2 * 1024 + row] - lse0) + (s - logf(g_sumexp[1024 + row]));
    } else if (t < 200000) {
        int ti = t - 40000;
        const bf16* h = g_H + OFF_H2 + (size_t)row * 64;
        float s = wdot(h, w2 + (size_t)ti * 64, 64, lane) + b2[ti];
        lp = (g_cl[1 * 1024 + row] - lse0) + (s - logf(g_sumexp[2048 + row]));
    } else {
        int ti = t - 200000;
        const bf16* h = g_H + OFF_H3 + (size_t)row * 16;
        float s = wdot(h, w3 + (size_t)ti * 16, 16, lane) + b3[ti];
        lp = (g_cl[0 * 1024 + row] - lse0) + (s - logf(g_sumexp[3072 + row]));
    }
    if (lane == 0) out[row] = -lp;
}

// ---------------------------------------------------------------------------
extern "C" void kernel_launch(void* const* d_in, const int* in_sizes, int n_in,
                              void* d_out, int out_size)
{
    const float* hidden    = (const float*)d_in[0];
    const int*   target    = (const int*)  d_in[1];
    const float* head_w    = (const float*)d_in[2];
    const float* head_b    = (const float*)d_in[3];
    const float* cluster_w = (const float*)d_in[4];
    const float* cluster_b = (const float*)d_in[5];
    const float* proj0     = (const float*)d_in[6];
    const float* proj1     = (const float*)d_in[7];
    const float* proj2     = (const float*)d_in[8];
    const float* proj3     = (const float*)d_in[9];
    const float* w1        = (const float*)d_in[10];
    const float* b1        = (const float*)d_in[11];
    const float* w2        = (const float*)d_in[12];
    const float* b2        = (const float*)d_in[13];
    const float* w3        = (const float*)d_in[14];
    const float* b3        = (const float*)d_in[15];
    float* out = (float*)d_out;

    // smem = bias + Bs + Stage(16w * S * 32 * (KC+8) * 2)
    // head S=2: 256 + 132096 + 81920            = 214272
    // t1   S=3: 512 + 67584  + 122880           = 190976
    // t2   S=4: 512 + 18432  + 163840           = 182784
    // t3   S=4: 512 + 6144   + 98304            = 104960
    const int SZ_BIG   = 214272;
    const int SZ_SMALL = 182784;

    static bool attr_done = false;
    if (!attr_done) {
        cudaFuncSetAttribute(vocab_big,
            cudaFuncAttributeMaxDynamicSharedMemorySize, SZ_BIG);
        cudaFuncSetAttribute(vocab_small,
            cudaFuncAttributeMaxDynamicSharedMemorySize, SZ_SMALL);
        attr_done = true;
    }

    proj_kernel<<<dim3(22, 8), 256>>>(hidden, proj0, proj1, proj2, proj3);

    // head 626 CTAs (first) + t1 314 CTAs = 940
    vocab_big<<<940, 512, SZ_BIG>>>(head_w, cluster_w, head_b, cluster_b, w1, b1);
    // t2 1250 CTAs + t3 530 CTAs = 1780
    vocab_small<<<1780, 512, SZ_SMALL>>>(w2, b2, w3, b3);

    finalize_kernel<<<128, 256>>>(target, head_w, head_b,
                                  w1, b1, w2, b2, w3, b3, out);
}

// round 16
// speedup vs baseline: 1.1032x; 1.1032x over previous
#include <cuda_runtime.h>
#include <cuda_bf16.h>
#include <mma.h>
#include <cstdint>

using namespace nvcuda;
typedef __nv_bfloat16 bf16;

#define OFF_H0 0
#define OFF_H1 1048576            // 1024*1024
#define OFF_H2 1310720            // +1024*256
#define OFF_H3 1376256            // +1024*16
// total used: 1376256 + 1024*16 = 1392640

__device__ __align__(1024) bf16  g_H[1392640];
__device__ float g_sumexp[4096];
__device__ float g_cl[3072];      // head logits for cols 20000..20002 (cluster)

__device__ __forceinline__ void cp16s(bf16* dst, const bf16* src) {
    unsigned d = (unsigned)__cvta_generic_to_shared(dst);
    asm volatile("cp.async.cg.shared.global [%0], [%1], 16;" :: "r"(d), "l"(src));
}
#define CP_COMMIT() asm volatile("cp.async.commit_group;")
template<int N> __device__ __forceinline__ void cp_wait() {
    asm volatile("cp.async.wait_group %0;" :: "n"(N));
}

// ---------------------------------------------------------------------------
// Barrier-free weight-stationary vocab GEMM + fused exp-sum (device body).
//   NB vocab rows per block; W slab + bias resident in smem (one barrier).
//   512 threads = 16 warps, WM x WN (WN=NB/64); warp tile 32 x 64 (acc[2][4]).
//   A staged per KC chunk into a WARP-PRIVATE S-stage ring of smem buffers via
//   per-warp cp.async. KC=64 for K>=64 (R16): halves per-chunk overhead and
//   doubles uninterrupted LDSM/HMMA runs; head keeps KC=32 (smem budget).
//   Epilogue: register-resident exp+bias on mma.16816 accumulator layout,
//   quad shfl-reduce, one atomicAdd per row. Head block n0=19968 also writes
//   cols 20000..20002 logits to g_cl (cluster logits for finalize).
// smem: bias[NB] | Bs[NB x (K+8)] | Stage[16w x S x 32 x (KC+8)]
// ---------------------------------------------------------------------------
template<int K, int NB, int MS, int S, int KC>
__device__ __forceinline__ void vocab_body(
        int bx, int by, char* smem,
        int h_off, const float* __restrict__ W, const float* __restrict__ W2,
        const float* __restrict__ bias, const float* __restrict__ bias2,
        int split, int V, int cidx)
{
    constexpr int KP    = K + 8;
    constexpr int WN    = NB / 64;            // 1 or 2
    constexpr int WM    = 16 / WN;            // 16 or 8
    constexpr int ROWS  = WM * 32;            // tokens per pass
    constexpr int NPASS = 1024 / ROWS;
    constexpr int PPB   = NPASS / MS;         // passes per block
    constexpr int NCH   = K / KC;
    constexpr int KP2   = KC + 8;
    constexpr int CPL   = KC / 8;             // cp.async per lane per chunk
    constexpr int QR    = KC / 8;             // uint4 per row
    constexpr int TOTAL = PPB * NCH;          // chunks per block

    float* bias_s = (float*)smem;
    bf16*  Bs     = (bf16*)(smem + NB * 4);
    bf16*  Stage  = (bf16*)(smem + NB * 4 + NB * KP * 2);

    const int tid = threadIdx.x, wid = tid >> 5, lane = tid & 31;
    const int wm = wid / WN, wn = wid % WN;
    const int n0 = bx * NB;
    const bf16* __restrict__ H = g_H + h_off;

    bf16* stg_base = Stage + wid * S * 32 * KP2;

    auto issue_chunk = [&](int gc) {
        int pass = by * PPB + gc / NCH;
        int ch   = gc % NCH;
        bf16* dst = stg_base + (gc % S) * 32 * KP2;
        const bf16* src = H + (size_t)(pass * ROWS + wm * 32) * K + ch * KC;
        #pragma unroll
        for (int i = 0; i < CPL; i++) {
            int idx = lane + i * 32;
            int r = idx / QR, q = idx % QR;
            cp16s(dst + r * KP2 + q * 8, src + (size_t)r * K + q * 8);
        }
        CP_COMMIT();
    };
    #pragma unroll
    for (int s = 0; s < S; s++) {
        if (s < TOTAL) issue_chunk(s);
        else           CP_COMMIT();
    }

    if (tid < NB) {
        int v = n0 + tid;
        float bv = 0.0f;
        if (v < split)  bv = bias[v];
        else if (v < V) bv = bias2[v - split];
        bias_s[tid] = bv;
    }
    // weight slab fp32 -> bf16 (once per block)
    for (int idx = tid; idx < NB * K / 4; idx += 512) {
        int r = idx / (K / 4), q = idx % (K / 4);
        int v = n0 + r;
        float4 val = make_float4(0.f, 0.f, 0.f, 0.f);
        if (v < split)  val = *(const float4*)(W + (size_t)v * K + q * 4);
        else if (v < V) val = *(const float4*)(W2 + (size_t)(v - split) * K + q * 4);
        __nv_bfloat162 lo = __floats2bfloat162_rn(val.x, val.y);
        __nv_bfloat162 hi = __floats2bfloat162_rn(val.z, val.w);
        uint2 pk; pk.x = *(unsigned*)&lo; pk.y = *(unsigned*)&hi;
        *(uint2*)(Bs + r * KP + q * 4) = pk;
    }
    __syncthreads();   // the only block-wide barrier

    const int qrow = lane >> 2;          // 0..7
    const int c2   = (lane & 3) * 2;

    for (int pp = 0; pp < PPB; pp++) {
        const int m0 = (by * PPB + pp) * ROWS + wm * 32;

        wmma::fragment<wmma::accumulator, 16, 16, 16, float> acc[2][4];
        #pragma unroll
        for (int i = 0; i < 2; i++)
            #pragma unroll
            for (int j = 0; j < 4; j++) wmma::fill_fragment(acc[i][j], 0.0f);

        for (int ch = 0; ch < NCH; ch++) {
            const int gc = pp * NCH + ch;
            cp_wait<S - 1>();    // chunk gc complete (in-order groups)
            __syncwarp();        // publish copied smem warp-wide
            const bf16* stg = stg_base + (gc % S) * 32 * KP2;

            #pragma unroll
            for (int ksl = 0; ksl < KC / 16; ksl++) {
                wmma::fragment<wmma::matrix_a, 16, 16, 16, bf16, wmma::row_major> af[2];
                #pragma unroll
                for (int i = 0; i < 2; i++)
                    wmma::load_matrix_sync(af[i], stg + (i * 16) * KP2 + ksl * 16, KP2);
                #pragma unroll
                for (int j = 0; j < 4; j++) {
                    wmma::fragment<wmma::matrix_b, 16, 16, 16, bf16, wmma::col_major> bfr;
                    wmma::load_matrix_sync(bfr,
                        Bs + (wn * 64 + j * 16) * KP + ch * KC + ksl * 16, KP);
                    #pragma unroll
                    for (int i = 0; i < 2; i++)
                        wmma::mma_sync(acc[i][j], af[i], bfr, acc[i][j]);
                }
            }
            __syncwarp();        // LDSMs done before buffer reuse
            if (gc + S < TOTAL) issue_chunk(gc + S);
            else                CP_COMMIT();   // keep group counting uniform
        }

        // register-resident epilogue: exp + bias on fragment regs, quad reduce
        #pragma unroll
        for (int i = 0; i < 2; i++) {
            float sA = 0.0f, sB = 0.0f;   // rows qrow, qrow+8 of this 16-tile
            #pragma unroll
            for (int j = 0; j < 4; j++) {
                const float* x = acc[i][j].x;
                int cb = wn * 64 + j * 16 + c2;
                if (n0 + cb < V) {
                    float b = bias_s[cb];
                    sA += __expf(x[0] + b); sB += __expf(x[2] + b);
                }
                if (n0 + cb + 1 < V) {
                    float b = bias_s[cb + 1];
                    sA += __expf(x[1] + b); sB += __expf(x[3] + b);
                }
                if (n0 + cb + 8 < V) {
                    float b = bias_s[cb + 8];
                    sA += __expf(x[4] + b); sB += __expf(x[6] + b);
                }
                if (n0 + cb + 9 < V) {
                    float b = bias_s[cb + 9];
                    sA += __expf(x[5] + b); sB += __expf(x[7] + b);
                }
            }
            sA += __shfl_xor_sync(0xffffffffu, sA, 1);
            sA += __shfl_xor_sync(0xffffffffu, sA, 2);
            sB += __shfl_xor_sync(0xffffffffu, sB, 1);
            sB += __shfl_xor_sync(0xffffffffu, sB, 2);
            if ((lane & 3) == 0) {
                atomicAdd(&g_sumexp[cidx * 1024 + m0 + i * 16 + qrow], sA);
                atomicAdd(&g_sumexp[cidx * 1024 + m0 + i * 16 + qrow + 8], sB);
            }
        }

        // cluster-logit extraction (head block covering cols 20000..20002 only)
        if (cidx == 0 && n0 == 19968) {
            #pragma unroll
            for (int i = 0; i < 2; i++) {
                int r0 = m0 + i * 16 + qrow, r1 = r0 + 8;
                #pragma unroll
                for (int j = 0; j < 4; j++) {
                    const float* x = acc[i][j].x;
                    int cb = wn * 64 + j * 16 + c2;
                    int g = n0 + cb;
                    #pragma unroll
                    for (int t = 0; t < 4; t++) {
                        static const int co[4] = {0, 1, 8, 9};
                        int gc2 = g + co[t];
                        if (gc2 >= 20000 && gc2 < 20003) {
                            int s = gc2 - 20000;
                            g_cl[s * 1024 + r0] = x[t < 2 ? t : t + 2] + bias_s[cb + co[t]];
                            g_cl[s * 1024 + r1] = x[t < 2 ? t + 2 : t + 4] + bias_s[cb + co[t]];
                        }
                    }
                }
            }
        }
    }
}

// Fused launch 1: head (626 CTAs, longest, launched first) + tail1 (314 CTAs)
__global__ __launch_bounds__(512) void vocab_big(
        const float* __restrict__ head_w, const float* __restrict__ cluster_w,
        const float* __restrict__ head_b, const float* __restrict__ cluster_b,
        const float* __restrict__ w1, const float* __restrict__ b1)
{
    extern __shared__ char smem[];
    int bx = blockIdx.x;
    if (bx < 626) {
        vocab_body<1024, 64, 2, 2, 32>(bx % 313, bx / 313, smem, OFF_H0,
                                       head_w, cluster_w, head_b, cluster_b,
                                       20000, 20003, 0);
    } else {
        int b = bx - 626;
        vocab_body<256, 128, 2, 2, 64>(b % 157, b / 157, smem, OFF_H1,
                                       w1, w1, b1, b1, 20000, 20000, 1);
    }
}

// Fused launch 2: tail2 (1250 CTAs) + tail3 (530 CTAs)
__global__ __launch_bounds__(512) void vocab_small(
        const float* __restrict__ w2, const float* __restrict__ b2,
        const float* __restrict__ w3, const float* __restrict__ b3)
{
    extern __shared__ char smem[];
    int bx = blockIdx.x;
    if (bx < 1250) {
        vocab_body<64, 128, 1, 2, 64>(bx, 0, smem, OFF_H2,
                                      w2, w2, b2, b2, 160000, 160000, 2);
    } else {
        vocab_body<16, 128, 1, 4, 16>(bx - 1250, 0, smem, OFF_H3,
                                      w3, w3, b3, b3, 67735, 67735, 3);
    }
}

// ---------------------------------------------------------------------------
// Fused projection GEMM (block (0,0) also zeroes g_sumexp).
// ---------------------------------------------------------------------------
#define AP 40
#define BPP 72
#define CPJ 68

__global__ __launch_bounds__(256) void proj_kernel(const float* __restrict__ A,
        const float* __restrict__ P0, const float* __restrict__ P1,
        const float* __restrict__ P2, const float* __restrict__ P3)
{
    __shared__ __align__(16) float s_c[128 * CPJ];
    bf16* As = (bf16*)s_c;
    bf16* Bs = As + 128 * AP;

    if (blockIdx.x == 0 && blockIdx.y == 0) {
        #pragma unroll
        for (int i = 0; i < 16; i++) g_sumexp[threadIdx.x + i * 256] = 0.0f;
    }

    int bx = blockIdx.x;
    const float* B; int Nout, h_off, n0;
    if (bx < 16)       { B = P0; Nout = 1024; h_off = OFF_H0; n0 = bx * 64; }
    else if (bx < 20)  { B = P1; Nout = 256;  h_off = OFF_H1; n0 = (bx - 16) * 64; }
    else if (bx == 20) { B = P2; Nout = 64;   h_off = OFF_H2; n0 = 0; }
    else               { B = P3; Nout = 16;   h_off = OFF_H3; n0 = 0; }

    const int tid = threadIdx.x;
    const int warpId = tid >> 5;
    const int wm = warpId & 3, wn = warpId >> 2;
    const int m0 = blockIdx.y * 128;
    const int K = 1024;

    wmma::fragment<wmma::accumulator, 16, 16, 16, float> acc[2][2];
    #pragma unroll
    for (int i = 0; i < 2; i++)
        #pragma unroll
        for (int j = 0; j < 2; j++) wmma::fill_fragment(acc[i][j], 0.0f);

    for (int kt = 0; kt < K; kt += 32) {
        #pragma unroll
        for (int i = 0; i < 4; i++) {
            int idx = tid + i * 256;
            int r = idx >> 3, kq = (idx & 7) << 2;
            float4 v = *(const float4*)(A + (size_t)(m0 + r) * K + kt + kq);
            bf16* d = As + r * AP + kq;
            d[0] = __float2bfloat16(v.x); d[1] = __float2bfloat16(v.y);
            d[2] = __float2bfloat16(v.z); d[3] = __float2bfloat16(v.w);
        }
        #pragma unroll
        for (int i = 0; i < 2; i++) {
            int idx = tid + i * 256;
            int kr = idx >> 4, nq = (idx & 15) << 2;
            int n = n0 + nq;
            float4 v = make_float4(0.f, 0.f, 0.f, 0.f);
            if (n < Nout) v = *(const float4*)(B + (size_t)(kt + kr) * Nout + n);
            bf16* d = Bs + kr * BPP + nq;
            d[0] = __float2bfloat16(v.x); d[1] = __float2bfloat16(v.y);
            d[2] = __float2bfloat16(v.z); d[3] = __float2bfloat16(v.w);
        }
        __syncthreads();
        #pragma unroll
        for (int kk = 0; kk < 32; kk += 16) {
            wmma::fragment<wmma::matrix_a, 16, 16, 16, bf16, wmma::row_major> af[2];
            wmma::fragment<wmma::matrix_b, 16, 16, 16, bf16, wmma::row_major> bfr[2];
            #pragma unroll
            for (int i = 0; i < 2; i++)
                wmma::load_matrix_sync(af[i], As + (wm * 32 + i * 16) * AP + kk, AP);
            #pragma unroll
            for (int j = 0; j < 2; j++)
                wmma::load_matrix_sync(bfr[j], Bs + kk * BPP + wn * 32 + j * 16, BPP);
            #pragma unroll
            for (int i = 0; i < 2; i++)
                #pragma unroll
                for (int j = 0; j < 2; j++)
                    wmma::mma_sync(acc[i][j], af[i], bfr[j], acc[i][j]);
        }
        __syncthreads();
    }

    #pragma unroll
    for (int i = 0; i < 2; i++)
        #pragma unroll
        for (int j = 0; j < 2; j++)
            wmma::store_matrix_sync(s_c + (wm * 32 + i * 16) * CPJ + wn * 32 + j * 16,
                                    acc[i][j], CPJ, wmma::mem_row_major);
    __syncthreads();

    bf16* Hh = g_H + h_off;
    for (int idx = tid; idx < 128 * 64; idx += 256) {
        int r = idx >> 6, c = idx & 63;
        int n = n0 + c;
        if (n < Nout)
            Hh[(size_t)(m0 + r) * Nout + n] = __float2bfloat16(s_c[r * CPJ + c]);
    }
}

// ---------------------------------------------------------------------------
// Finalize: per-row target logit + combine with logsumexps. One warp per row.
// Cluster logits come precomputed from the head GEMM (g_cl).
// ---------------------------------------------------------------------------
__device__ __forceinline__ float wdot(const bf16* h, const float* w, int K, int lane) {
    float s = 0.0f;
    #pragma unroll 8
    for (int k = lane; k < K; k += 32)
        s += __bfloat162float(h[k]) * w[k];
    #pragma unroll
    for (int o = 16; o; o >>= 1) s += __shfl_xor_sync(0xffffffffu, s, o);
    return s;
}

__global__ __launch_bounds__(256) void finalize_kernel(const int* __restrict__ target,
    const float* __restrict__ head_w,   const float* __restrict__ head_b,
    const float* __restrict__ w1, const float* __restrict__ b1,
    const float* __restrict__ w2, const float* __restrict__ b2,
    const float* __restrict__ w3, const float* __restrict__ b3,
    float* __restrict__ out)
{
    int warpId = threadIdx.x >> 5, lane = threadIdx.x & 31;
    int row = blockIdx.x * 8 + warpId;
    if (row >= 1024) return;

    const bf16* h0 = g_H + (size_t)row * 1024;

    float lse0 = logf(g_sumexp[row]);
    int t = target[row];
    float lp;
    if (t < 20000) {
        float s = wdot(h0, head_w + (size_t)t * 1024, 1024, lane) + head_b[t];
        lp = s - lse0;
    } else if (t < 40000) {
        int ti = t - 20000;
        const bf16* h = g_H + OFF_H1 + (size_t)row * 256;
        float s = wdot(h, w1 + (size_t)ti * 256, 256, lane) + b1[ti];
        lp = (g_cl[2 * 1024 + row] - lse0) + (s - logf(g_sumexp[1024 + row]));
    } else if (t < 200000) {
        int ti = t - 40000;
        const bf16* h = g_H + OFF_H2 + (size_t)row * 64;
        float s = wdot(h, w2 + (size_t)ti * 64, 64, lane) + b2[ti];
        lp = (g_cl[1 * 1024 + row] - lse0) + (s - logf(g_sumexp[2048 + row]));
    } else {
        int ti = t - 200000;
        const bf16* h = g_H + OFF_H3 + (size_t)row * 16;
        float s = wdot(h, w3 + (size_t)ti * 16, 16, lane) + b3[ti];
        lp = (g_cl[0 * 1024 + row] - lse0) + (s - logf(g_sumexp[3072 + row]));
    }
    if (lane == 0) out[row] = -lp;
}

// ---------------------------------------------------------------------------
extern "C" void kernel_launch(void* const* d_in, const int* in_sizes, int n_in,
                              void* d_out, int out_size)
{
    const float* hidden    = (const float*)d_in[0];
    const int*   target    = (const int*)  d_in[1];
    const float* head_w    = (const float*)d_in[2];
    const float* head_b    = (const float*)d_in[3];
    const float* cluster_w = (const float*)d_in[4];
    const float* cluster_b = (const float*)d_in[5];
    const float* proj0     = (const float*)d_in[6];
    const float* proj1     = (const float*)d_in[7];
    const float* proj2     = (const float*)d_in[8];
    const float* proj3     = (const float*)d_in[9];
    const float* w1        = (const float*)d_in[10];
    const float* b1        = (const float*)d_in[11];
    const float* w2        = (const float*)d_in[12];
    const float* b2        = (const float*)d_in[13];
    const float* w3        = (const float*)d_in[14];
    const float* b3        = (const float*)d_in[15];
    float* out = (float*)d_out;

    // smem = bias + Bs + Stage(16w * S * 32 * (KC+8) * 2)
    // head S=2 KC=32: 256 + 132096 + 81920  = 214272
    // t1   S=2 KC=64: 512 + 67584  + 147456 = 215552
    // t2   S=2 KC=64: 512 + 18432  + 147456 = 166400
    // t3   S=4 KC=16: 512 + 6144   + 49152  = 55808
    const int SZ_BIG   = 215552;
    const int SZ_SMALL = 166400;

    static cudaStream_t s2 = nullptr;
    static cudaEvent_t eFork = nullptr, eJoin = nullptr;
    static bool init_done = false;
    if (!init_done) {
        cudaFuncSetAttribute(vocab_big,
            cudaFuncAttributeMaxDynamicSharedMemorySize, SZ_BIG);
        cudaFuncSetAttribute(vocab_small,
            cudaFuncAttributeMaxDynamicSharedMemorySize, SZ_SMALL);
        cudaStreamCreateWithFlags(&s2, cudaStreamNonBlocking);
        cudaEventCreateWithFlags(&eFork, cudaEventDisableTiming);
        cudaEventCreateWithFlags(&eJoin, cudaEventDisableTiming);
        init_done = true;
    }

    proj_kernel<<<dim3(22, 8), 256>>>(hidden, proj0, proj1, proj2, proj3);
    cudaEventRecord(eFork, 0);
    cudaStreamWaitEvent(s2, eFork, 0);

    // head 626 CTAs (first) + t1 314 CTAs = 940 on the main stream;
    // t2 1250 + t3 530 = 1780 on s2: tail-fills SMs as vocab_big drains.
    vocab_big<<<940, 512, SZ_BIG>>>(head_w, cluster_w, head_b, cluster_b, w1, b1);
    vocab_small<<<1780, 512, SZ_SMALL, s2>>>(w2, b2, w3, b3);

    cudaEventRecord(eJoin, s2);
    cudaStreamWaitEvent(0, eJoin, 0);

    finalize_kernel<<<128, 256>>>(target, head_w, head_b,
                                  w1, b1, w2, b2, w3, b3, out);
}